// round 16
// baseline (speedup 1.0000x reference)
#include <cuda_runtime.h>
#include <cuda_fp16.h>
#include <cstdint>

// Problem dims (fixed by dataset): N=20000, E=320000, B=16,
// node_dim=256, cond_dim=512, out_dim=256.
#define NMAX 20000
#define EMAX 320000
#define BMAX 16

// Scratch (allocation-free rule: __device__ globals)
__device__ __align__(16) __half g_xh[(size_t)NMAX * 256];  // post-LN x, fp16
__device__ __align__(16) float g_gamma[BMAX * 256];
__device__ __align__(16) float g_beta[BMAX * 256];
__device__ __align__(16) __half g_Wf[256 * 256];   // W^T fp16, [n][k]
__device__ int   g_cnt[NMAX];
__device__ int   g_off[NMAX + 1];
__device__ int   g_cur[NMAX];
__device__ int   g_blk[256];
__device__ __align__(16) int2 g_edge[EMAX];   // (src, w) packed, CSR order

// software grid barrier state (generation-based; persists across replays)
__device__ unsigned g_arrive;
__device__ volatile unsigned g_gen;

#define SMEM_SWIZZLE_128B(off) ((off) ^ (((off) >> 3) & 0x70))

// warp-level fp16 MMA, fp32 accum (baseline PTX, works on compute_103)
__device__ __forceinline__ void mma16816(float* c, const uint32_t* a,
                                         const uint32_t* b) {
    asm volatile(
        "mma.sync.aligned.m16n8k16.row.col.f32.f16.f16.f32 "
        "{%0,%1,%2,%3},{%4,%5,%6,%7},{%8,%9},{%0,%1,%2,%3};"
        : "+f"(c[0]), "+f"(c[1]), "+f"(c[2]), "+f"(c[3])
        : "r"(a[0]), "r"(a[1]), "r"(a[2]), "r"(a[3]), "r"(b[0]), "r"(b[1]));
}
__device__ __forceinline__ void ldsm_x4(uint32_t* r, uint32_t addr) {
    asm volatile("ldmatrix.sync.aligned.m8n8.x4.shared.b16 {%0,%1,%2,%3}, [%4];"
                 : "=r"(r[0]), "=r"(r[1]), "=r"(r[2]), "=r"(r[3]) : "r"(addr));
}
__device__ __forceinline__ uint32_t smem_to_u32(const void* p) {
    uint32_t a;
    asm("{ .reg .u64 t; cvta.to.shared.u64 t, %1; cvt.u32.u64 %0, t; }"
        : "=r"(a) : "l"(p));
    return a;
}
#define CP_ASYNC16(dst, src) \
    asm volatile("cp.async.cg.shared.global [%0], [%1], 16;" \
                 :: "r"(dst), "l"(src) : "memory")
#define CP_COMMIT() asm volatile("cp.async.commit_group;" ::: "memory")
#define CP_WAIT1() asm volatile("cp.async.wait_group 1;" ::: "memory")
#define CP_WAIT0() asm volatile("cp.async.wait_group 0;" ::: "memory")

// ---------------------------------------------------------------------------
// 1. prep: blocks 0..63 transpose W->fp16; blocks 64..95 FiLM params.
// ---------------------------------------------------------------------------
__global__ void prep_kernel(const float* __restrict__ W,
                            const float* __restrict__ cond,
                            const float* __restrict__ Wc,
                            const float* __restrict__ bc, int B) {
    int blk = blockIdx.x;
    int tid = threadIdx.x;
    if (blk < 64) {
        __shared__ float t[32][33];
        int bi = blk & 7;            // n-tile
        int bj = blk >> 3;           // k-tile
        int tx = tid & 31, ty = tid >> 5;   // 32 x 8
#pragma unroll
        for (int i = 0; i < 4; i++)
            t[ty + i * 8][tx] = W[(size_t)(bj * 32 + ty + i * 8) * 256 + bi * 32 + tx];
        __syncthreads();
#pragma unroll
        for (int i = 0; i < 4; i++) {
            int n = bi * 32 + ty + i * 8;
            int k = bj * 32 + tx;
            g_Wf[(size_t)n * 256 + k] = __float2half_rn(t[tx][ty + i * 8]);
        }
    } else {
        int idx = (blk - 64) * 256 + tid;
        if (idx >= B * 512) return;
        int b = idx >> 9;
        int o = idx & 511;
        const float* c = cond + b * 512;
        float acc = bc[o];
#pragma unroll 4
        for (int k = 0; k < 512; k++) acc = fmaf(c[k], Wc[k * 512 + o], acc);
        if (o < 256) g_gamma[b * 256 + o] = acc + 1.0f;
        else         g_beta[b * 256 + (o - 256)] = acc;
    }
}

// ---------------------------------------------------------------------------
// 2. Fused CSR build: zero -> hist -> scan -> fill, ONE persistent kernel.
//    148 blocks x 256 threads; runs ALONE (no concurrent full-RF kernel), so
//    all blocks are resident and the software grid barrier is safe.
// ---------------------------------------------------------------------------
#define CSR_BLOCKS 148

__device__ __forceinline__ void gbar() {
    __syncthreads();
    if (threadIdx.x == 0) {
        __threadfence();
        unsigned gen = g_gen;
        if (atomicAdd(&g_arrive, 1u) == (unsigned)(CSR_BLOCKS - 1)) {
            g_arrive = 0;
            __threadfence();
            g_gen = gen + 1;
        } else {
            while (g_gen == gen) { __nanosleep(64); }
        }
    }
    __syncthreads();
}

__global__ void __launch_bounds__(256, 1)
csr_kernel(const int* __restrict__ ni, const int* __restrict__ nj,
           const float* __restrict__ ew, const float* __restrict__ ep,
           int N, int E) {
    int tid = threadIdx.x, bid = blockIdx.x;
    int gthreads = CSR_BLOCKS * 256;
    int gid = bid * 256 + tid;

    // phase 0: zero counters
    for (int i = gid; i < N; i += gthreads) { g_cnt[i] = 0; g_cur[i] = 0; }
    gbar();

    // phase 1: histogram
    for (int e = gid; e < E; e += gthreads) atomicAdd(&g_cnt[ni[e]], 1);
    gbar();

    // phase 2: exclusive scan (chunk of <=256 per block + cross-block prefix)
    __shared__ int sv[256];
    __shared__ int sprefix;
    int chunk = (N + CSR_BLOCKS - 1) / CSR_BLOCKS;   // 136 for N=20000
    int base = bid * chunk;
    int idx = base + tid;
    int v = (tid < chunk && idx < N) ? g_cnt[idx] : 0;
    sv[tid] = v;
    __syncthreads();
#pragma unroll
    for (int o = 1; o < 256; o <<= 1) {
        int t = (tid >= o) ? sv[tid - o] : 0;
        __syncthreads();
        sv[tid] += t;
        __syncthreads();
    }
    if (tid == 255) g_blk[bid] = sv[255];
    gbar();
    if (tid < 32) {
        int acc = 0;
        for (int t = tid; t < bid; t += 32) acc += g_blk[t];
#pragma unroll
        for (int o = 16; o; o >>= 1) acc += __shfl_xor_sync(0xffffffffu, acc, o);
        if (tid == 0) sprefix = acc;
    }
    __syncthreads();
    if (tid < chunk && idx < N) g_off[idx] = sv[tid] - v + sprefix;
    if (gid == 0) g_off[N] = E;
    gbar();

    // phase 3: fill CSR payloads
    for (int e = gid; e < E; e += gthreads) {
        int dst = ni[e];
        int p = atomicAdd(&g_cur[dst], 1);
        g_edge[g_off[dst] + p] = make_int2(nj[e], __float_as_int(ew[e] * ep[e]));
    }
}

// ---------------------------------------------------------------------------
// 3. Tensor GEMM (mma.sync fp16, single pass: X = Af @ Wf) + LN/FiLM/ReLU.
// ---------------------------------------------------------------------------
#define SM_W0 0
#define SM_W1 16384
#define SM_AH 32768
#define SM_ST 36864
#define SM_TOTAL (36864 + 512)

__device__ __forceinline__ void issue_w_chunk(uint32_t wbuf, int kt, int tid) {
#pragma unroll
    for (int it = 0; it < 4; it++) {
        int item = it * 256 + tid;
        int n = item >> 2;
        int c = item & 3;
        uint32_t off = (uint32_t)((n & 127) * 128 + (n >> 7) * 64 + c * 16);
        uint32_t sw = SMEM_SWIZZLE_128B(off);
        size_t go = (size_t)n * 512 + (size_t)kt * 64 + c * 16;   // bytes
        CP_ASYNC16(wbuf + sw, (const char*)g_Wf + go);
    }
    CP_COMMIT();
}

__global__ void __launch_bounds__(256, 2)
gemm_ln_kernel(const float* __restrict__ A,
               const int* __restrict__ batch_ids, int N) {
    extern __shared__ char sm[];
    uint32_t smb = smem_to_u32(sm);
    float* s_sum = (float*)(sm + SM_ST);        // [64]
    float* s_sq  = (float*)(sm + SM_ST + 256);  // [64]

    int tid = threadIdx.x;
    int wid = tid >> 5, lane = tid & 31;
    int mw = wid >> 2;           // 0..1  m-warp
    int nw = wid & 3;            // 0..3  n-warp
    int m0 = blockIdx.x * 64;

    if (tid < 128) ((float*)(sm + SM_ST))[tid] = 0.0f;

    // ldmatrix per-lane addressing
    int g = lane >> 3;
    int lr = lane & 7;
    uint32_t axor = (uint32_t)(lr << 4);
    uint32_t a_row[2];
#pragma unroll
    for (int tm = 0; tm < 2; tm++)
        a_row[tm] = (uint32_t)((tm * 16 + (g & 1) * 8 + lr) * 128);
    uint32_t a_low_base = (uint32_t)(mw * 64 + (g >> 1) * 16);
    uint32_t b_row[4];
#pragma unroll
    for (int np = 0; np < 4; np++)
        b_row[np] = (uint32_t)((((nw & 1) * 64 + np * 16 + ((g >> 1) & 1) * 8 + lr)) * 128);
    uint32_t b_low_base = (uint32_t)((nw >> 1) * 64 + (g & 1) * 16);

    // A prefetch mapping
    int pm = tid >> 2;
    int prow = m0 + pm;
    const float* aptr = A + (size_t)prow * 256 + (tid & 3) * 8;
    bool pvalid = (prow < N);
    uint32_t a_st_off = SMEM_SWIZZLE_128B(
        (uint32_t)((pm & 31) * 128 + (pm >> 5) * 64 + (tid & 3) * 16));

    float c[2][8][4];
#pragma unroll
    for (int i = 0; i < 2; i++)
#pragma unroll
        for (int j = 0; j < 8; j++)
#pragma unroll
            for (int q = 0; q < 4; q++) c[i][j][q] = 0.0f;

    // ---- prologue
    issue_w_chunk(smb + SM_W0, 0, tid);
    issue_w_chunk(smb + SM_W1, 1, tid);
    float4 aP0 = make_float4(0.f, 0.f, 0.f, 0.f);
    float4 aP1 = make_float4(0.f, 0.f, 0.f, 0.f);
    if (pvalid) {
        aP0 = *(const float4*)(aptr);
        aP1 = *(const float4*)(aptr + 4);
    }

    for (int kt = 0; kt < 8; kt++) {
        if (kt > 0) __syncthreads();
        if (kt >= 1 && kt + 1 < 8)
            issue_w_chunk(smb + SM_W0 + ((kt + 1) & 1) * 16384, kt + 1, tid);

        // store converted A(kt) fp16
        {
            float f[8] = {aP0.x, aP0.y, aP0.z, aP0.w, aP1.x, aP1.y, aP1.z, aP1.w};
            uint32_t h[4];
#pragma unroll
            for (int q = 0; q < 4; q++) {
                __half h0 = __float2half_rn(f[2 * q]);
                __half h1 = __float2half_rn(f[2 * q + 1]);
                h[q] = ((uint32_t)__half_as_ushort(h1) << 16) | __half_as_ushort(h0);
            }
            *(uint4*)(sm + SM_AH + a_st_off) = make_uint4(h[0], h[1], h[2], h[3]);
        }

        if (kt == 7) { CP_WAIT0(); } else { CP_WAIT1(); }
        __syncthreads();

        if (kt + 1 < 8 && pvalid) {
            aP0 = *(const float4*)(aptr + (kt + 1) * 32);
            aP1 = *(const float4*)(aptr + (kt + 1) * 32 + 4);
        }

        uint32_t wb = smb + SM_W0 + (kt & 1) * 16384;
#pragma unroll
        for (int ks = 0; ks < 2; ks++) {
            uint32_t alow = (a_low_base + (uint32_t)(ks * 32)) ^ axor;
            uint32_t blow = (b_low_base + (uint32_t)(ks * 32)) ^ axor;
            uint32_t ah0[4], ah1[4];
            ldsm_x4(ah0, smb + SM_AH + a_row[0] + alow);
            ldsm_x4(ah1, smb + SM_AH + a_row[1] + alow);
            uint32_t bf[4][4];
#pragma unroll
            for (int np = 0; np < 4; np++)
                ldsm_x4(bf[np], wb + b_row[np] + blow);

            // 16 independent accumulators per warp
#pragma unroll
            for (int np = 0; np < 4; np++) {
                mma16816(c[0][2 * np],     ah0, bf[np]);
                mma16816(c[0][2 * np + 1], ah0, bf[np] + 2);
                mma16816(c[1][2 * np],     ah1, bf[np]);
                mma16816(c[1][2 * np + 1], ah1, bf[np] + 2);
            }
        }
    }

    // ---- LN stats: quad-shuffle partials, smem atomics across n-warps ----
#pragma unroll
    for (int tm = 0; tm < 2; tm++) {
#pragma unroll
        for (int h = 0; h < 2; h++) {
            int rl = mw * 32 + tm * 16 + h * 8 + (lane >> 2);
            float ps = 0.f, pq = 0.f;
#pragma unroll
            for (int nt = 0; nt < 8; nt++) {
                float v0 = c[tm][nt][2 * h], v1 = c[tm][nt][2 * h + 1];
                ps += v0 + v1;
                pq = fmaf(v0, v0, fmaf(v1, v1, pq));
            }
            ps += __shfl_xor_sync(0xffffffffu, ps, 1);
            pq += __shfl_xor_sync(0xffffffffu, pq, 1);
            ps += __shfl_xor_sync(0xffffffffu, ps, 2);
            pq += __shfl_xor_sync(0xffffffffu, pq, 2);
            if ((lane & 3) == 0) {
                atomicAdd(&s_sum[rl], ps);
                atomicAdd(&s_sq[rl], pq);
            }
        }
    }
    __syncthreads();

    // ---- normalize + FiLM + ReLU from fragments -> g_xh (fp16) ----
#pragma unroll
    for (int tm = 0; tm < 2; tm++) {
#pragma unroll
        for (int h = 0; h < 2; h++) {
            int rl = mw * 32 + tm * 16 + h * 8 + (lane >> 2);
            int row = m0 + rl;
            if (row >= N) continue;
            float mu = s_sum[rl] * (1.0f / 256.0f);
            float var = fmaxf(s_sq[rl] * (1.0f / 256.0f) - mu * mu, 0.0f);
            float rs = rsqrtf(var + 1e-5f);
            int b = batch_ids[row];
            const float* gg = g_gamma + b * 256;
            const float* bb = g_beta + b * 256;
            __half2* xo = (__half2*)(g_xh + (size_t)row * 256);
#pragma unroll
            for (int nt = 0; nt < 8; nt++) {
                int col = nw * 64 + nt * 8 + (lane & 3) * 2;
                float2 gv = *(const float2*)(gg + col);
                float2 ev = *(const float2*)(bb + col);
                float2 o;
                o.x = fmaxf(fmaf((c[tm][nt][2 * h] - mu) * rs, gv.x, ev.x), 0.f);
                o.y = fmaxf(fmaf((c[tm][nt][2 * h + 1] - mu) * rs, gv.y, ev.y), 0.f);
                xo[col >> 1] = __float22half2_rn(o);
            }
        }
    }
}

// ---------------------------------------------------------------------------
// 4. Pull aggregation: warp per node, coalesced edge fetch + shfl broadcast.
// ---------------------------------------------------------------------------
__global__ void agg_kernel(float* __restrict__ out, int N) {
    int gw = (blockIdx.x * blockDim.x + threadIdx.x) >> 5;
    int lane = threadIdx.x & 31;
    if (gw >= N) return;
    int s = g_off[gw];
    int e = g_off[gw + 1];
    float acc[8] = {0.f, 0.f, 0.f, 0.f, 0.f, 0.f, 0.f, 0.f};

    for (int base = s; base < e; base += 32) {
        int cnt = min(32, e - base);
        int2 my = (lane < cnt) ? g_edge[base + lane] : make_int2(0, 0);
        int j = 0;
        for (; j + 2 <= cnt; j += 2) {
            int s0 = __shfl_sync(0xffffffffu, my.x, j);
            int w0i = __shfl_sync(0xffffffffu, my.y, j);
            int s1 = __shfl_sync(0xffffffffu, my.x, j + 1);
            int w1i = __shfl_sync(0xffffffffu, my.y, j + 1);
            uint4 v0 = *(const uint4*)((const char*)g_xh + (size_t)s0 * 512 + lane * 16);
            uint4 v1 = *(const uint4*)((const char*)g_xh + (size_t)s1 * 512 + lane * 16);
            float w0 = __int_as_float(w0i);
            float w1 = __int_as_float(w1i);
            const __half2* h0 = (const __half2*)&v0;
            const __half2* h1 = (const __half2*)&v1;
#pragma unroll
            for (int q = 0; q < 4; q++) {
                float2 f0 = __half22float2(h0[q]);
                float2 f1 = __half22float2(h1[q]);
                acc[2 * q]     = fmaf(f0.x, w0, fmaf(f1.x, w1, acc[2 * q]));
                acc[2 * q + 1] = fmaf(f0.y, w0, fmaf(f1.y, w1, acc[2 * q + 1]));
            }
        }
        if (j < cnt) {
            int s0 = __shfl_sync(0xffffffffu, my.x, j);
            int w0i = __shfl_sync(0xffffffffu, my.y, j);
            uint4 v0 = *(const uint4*)((const char*)g_xh + (size_t)s0 * 512 + lane * 16);
            float w0 = __int_as_float(w0i);
            const __half2* h0 = (const __half2*)&v0;
#pragma unroll
            for (int q = 0; q < 4; q++) {
                float2 f0 = __half22float2(h0[q]);
                acc[2 * q]     = fmaf(f0.x, w0, acc[2 * q]);
                acc[2 * q + 1] = fmaf(f0.y, w0, acc[2 * q + 1]);
            }
        }
    }

    float4 o0, o1;
    o0.x = fmaxf(acc[0], 0.f); o0.y = fmaxf(acc[1], 0.f);
    o0.z = fmaxf(acc[2], 0.f); o0.w = fmaxf(acc[3], 0.f);
    o1.x = fmaxf(acc[4], 0.f); o1.y = fmaxf(acc[5], 0.f);
    o1.z = fmaxf(acc[6], 0.f); o1.w = fmaxf(acc[7], 0.f);
    float4* o4 = (float4*)(out + (size_t)gw * 256 + lane * 8);
    o4[0] = o0;
    o4[1] = o1;
}

// ---------------------------------------------------------------------------
extern "C" void kernel_launch(void* const* d_in, const int* in_sizes, int n_in,
                              void* d_out, int out_size) {
    const float* node_feats = (const float*)d_in[0];
    const float* cond_feats = (const float*)d_in[1];
    const int*   batch_ids  = (const int*)d_in[2];
    const int*   node_j     = (const int*)d_in[3];
    const int*   node_i     = (const int*)d_in[4];
    const float* edge_w     = (const float*)d_in[5];
    const float* edge_p     = (const float*)d_in[6];
    const float* Wc         = (const float*)d_in[7];
    const float* bc         = (const float*)d_in[8];
    const float* Wl         = (const float*)d_in[9];
    float* out = (float*)d_out;

    int N = in_sizes[0] / 256;
    int B = in_sizes[1] / 512;
    int E = in_sizes[3];

    static int init_done = 0;
    if (!init_done) {
        cudaFuncSetAttribute(gemm_ln_kernel,
                             cudaFuncAttributeMaxDynamicSharedMemorySize, SM_TOTAL);
        init_done = 1;
    }

    // Single stream, 4 kernels. csr runs ALONE (grid barrier safety).
    prep_kernel<<<96, 256>>>(Wl, cond_feats, Wc, bc, B);
    csr_kernel<<<CSR_BLOCKS, 256>>>(node_i, node_j, edge_w, edge_p, N, E);
    gemm_ln_kernel<<<(N + 63) / 64, 256, SM_TOTAL>>>(node_feats, batch_ids, N);
    agg_kernel<<<(N * 32 + 255) / 256, 256>>>(out, N);
}

// round 17
// speedup vs baseline: 1.1504x; 1.1504x over previous
#include <cuda_runtime.h>
#include <cuda_fp16.h>
#include <cstdint>

// Problem dims (fixed by dataset): N=20000, E=320000, B=16,
// node_dim=256, cond_dim=512, out_dim=256.
#define NMAX 20000
#define EMAX 320000
#define BMAX 16

// Scratch (allocation-free rule: __device__ globals)
__device__ __align__(16) __half g_xh[(size_t)NMAX * 256];  // post-LN x, fp16
__device__ __align__(16) float g_gamma[BMAX * 256];
__device__ __align__(16) float g_beta[BMAX * 256];
__device__ __align__(16) __half g_Wf[256 * 256];   // W^T fp16, [n][k]
__device__ int   g_cnt[NMAX];
__device__ int   g_off[NMAX + 1];
__device__ int   g_cur[NMAX];
__device__ unsigned long long g_scan_desc[128];    // decoupled-lookback state
__device__ __align__(16) int2 g_edge[EMAX];        // (src, w) packed, CSR order

#define SMEM_SWIZZLE_128B(off) ((off) ^ (((off) >> 3) & 0x70))

// warp-level fp16 MMA, fp32 accum (baseline PTX, works on compute_103)
__device__ __forceinline__ void mma16816(float* c, const uint32_t* a,
                                         const uint32_t* b) {
    asm volatile(
        "mma.sync.aligned.m16n8k16.row.col.f32.f16.f16.f32 "
        "{%0,%1,%2,%3},{%4,%5,%6,%7},{%8,%9},{%0,%1,%2,%3};"
        : "+f"(c[0]), "+f"(c[1]), "+f"(c[2]), "+f"(c[3])
        : "r"(a[0]), "r"(a[1]), "r"(a[2]), "r"(a[3]), "r"(b[0]), "r"(b[1]));
}
__device__ __forceinline__ void ldsm_x4(uint32_t* r, uint32_t addr) {
    asm volatile("ldmatrix.sync.aligned.m8n8.x4.shared.b16 {%0,%1,%2,%3}, [%4];"
                 : "=r"(r[0]), "=r"(r[1]), "=r"(r[2]), "=r"(r[3]) : "r"(addr));
}
__device__ __forceinline__ uint32_t smem_to_u32(const void* p) {
    uint32_t a;
    asm("{ .reg .u64 t; cvta.to.shared.u64 t, %1; cvt.u32.u64 %0, t; }"
        : "=r"(a) : "l"(p));
    return a;
}
#define CP_ASYNC16(dst, src) \
    asm volatile("cp.async.cg.shared.global [%0], [%1], 16;" \
                 :: "r"(dst), "l"(src) : "memory")
#define CP_COMMIT() asm volatile("cp.async.commit_group;" ::: "memory")
#define CP_WAIT1() asm volatile("cp.async.wait_group 1;" ::: "memory")
#define CP_WAIT0() asm volatile("cp.async.wait_group 0;" ::: "memory")

// ---------------------------------------------------------------------------
// 1. prep: zero CSR state; blocks 0..63 transpose W->fp16; 64..95 FiLM.
// ---------------------------------------------------------------------------
__global__ void prep_kernel(const float* __restrict__ W,
                            const float* __restrict__ cond,
                            const float* __restrict__ Wc,
                            const float* __restrict__ bc, int B, int N) {
    int blk = blockIdx.x;
    int tid = threadIdx.x;
    int gid = blk * 256 + tid;
    for (int i = gid; i < N; i += gridDim.x * 256) { g_cnt[i] = 0; g_cur[i] = 0; }
    if (gid < 128) g_scan_desc[gid] = 0ULL;

    if (blk < 64) {
        __shared__ float t[32][33];
        int bi = blk & 7;            // n-tile
        int bj = blk >> 3;           // k-tile
        int tx = tid & 31, ty = tid >> 5;   // 32 x 8
#pragma unroll
        for (int i = 0; i < 4; i++)
            t[ty + i * 8][tx] = W[(size_t)(bj * 32 + ty + i * 8) * 256 + bi * 32 + tx];
        __syncthreads();
#pragma unroll
        for (int i = 0; i < 4; i++) {
            int n = bi * 32 + ty + i * 8;
            int k = bj * 32 + tx;
            g_Wf[(size_t)n * 256 + k] = __float2half_rn(t[tx][ty + i * 8]);
        }
    } else {
        int idx = (blk - 64) * 256 + tid;
        if (idx >= B * 512) return;
        int b = idx >> 9;
        int o = idx & 511;
        const float* c = cond + b * 512;
        float acc = bc[o];
#pragma unroll 4
        for (int k = 0; k < 512; k++) acc = fmaf(c[k], Wc[k * 512 + o], acc);
        if (o < 256) g_gamma[b * 256 + o] = acc + 1.0f;
        else         g_beta[b * 256 + (o - 256)] = acc;
    }
}

// ---------------------------------------------------------------------------
// 2. hist
// ---------------------------------------------------------------------------
__global__ void hist_kernel(const int* __restrict__ ni, int E) {
    int e = blockIdx.x * blockDim.x + threadIdx.x;
    if (e < E) atomicAdd(&g_cnt[ni[e]], 1);
}

// ---------------------------------------------------------------------------
// 3. Single-kernel exclusive scan with decoupled lookback.
//    flag (bits 32+): 1 = block aggregate, 2 = inclusive prefix.
// ---------------------------------------------------------------------------
__global__ void scan_kernel(int N, int E) {
    __shared__ int wsum[8];
    __shared__ int s_prefix;
    int tid = threadIdx.x, bid = blockIdx.x;
    int lane = tid & 31, wid = tid >> 5;
    int idx = bid * 256 + tid;
    int v = (idx < N) ? g_cnt[idx] : 0;
    int s = v;
#pragma unroll
    for (int o = 1; o < 32; o <<= 1) {
        int t = __shfl_up_sync(0xffffffffu, s, o);
        if (lane >= o) s += t;
    }
    if (lane == 31) wsum[wid] = s;
    __syncthreads();
    if (wid == 0) {
        int ws = (lane < 8) ? wsum[lane] : 0;
#pragma unroll
        for (int o = 1; o < 8; o <<= 1) {
            int t = __shfl_up_sync(0xffffffffu, ws, o);
            if (lane >= o) ws += t;
        }
        if (lane < 8) wsum[lane] = ws;
    }
    __syncthreads();
    int excl = s - v + (wid ? wsum[wid - 1] : 0);
    int total = wsum[7];

    if (tid == 0) {
        // publish aggregate immediately (helps successors' lookback)
        if (bid > 0)
            atomicExch(&g_scan_desc[bid],
                       (1ULL << 32) | (unsigned long long)(unsigned)total);
        int run = 0;
        if (bid > 0) {
            int j = bid - 1;
            while (j >= 0) {
                unsigned long long d;
                do { d = atomicAdd(&g_scan_desc[j], 0ULL); } while ((d >> 32) == 0ULL);
                run += (int)(unsigned)d;
                if ((d >> 32) == 2ULL) break;
                j--;
            }
        }
        s_prefix = run;
        atomicExch(&g_scan_desc[bid],
                   (2ULL << 32) | (unsigned long long)(unsigned)(run + total));
    }
    __syncthreads();
    if (idx < N) g_off[idx] = s_prefix + excl;
    if (idx == 0) g_off[N] = E;
}

// ---------------------------------------------------------------------------
// 4. fill: permute edge payloads into CSR order.
// ---------------------------------------------------------------------------
__global__ void fill_kernel(const int* __restrict__ ni,
                            const int* __restrict__ nj,
                            const float* __restrict__ ew,
                            const float* __restrict__ ep, int E) {
    int e = blockIdx.x * blockDim.x + threadIdx.x;
    if (e < E) {
        int dst = ni[e];
        int p = atomicAdd(&g_cur[dst], 1);
        g_edge[g_off[dst] + p] = make_int2(nj[e], __float_as_int(ew[e] * ep[e]));
    }
}

// ---------------------------------------------------------------------------
// 5. Tensor GEMM (mma.sync fp16, single pass: X = Af @ Wf) + LN/FiLM/ReLU.
// ---------------------------------------------------------------------------
#define SM_W0 0
#define SM_W1 16384
#define SM_AH 32768
#define SM_ST 36864
#define SM_TOTAL (36864 + 512)

__device__ __forceinline__ void issue_w_chunk(uint32_t wbuf, int kt, int tid) {
#pragma unroll
    for (int it = 0; it < 4; it++) {
        int item = it * 256 + tid;
        int n = item >> 2;
        int c = item & 3;
        uint32_t off = (uint32_t)((n & 127) * 128 + (n >> 7) * 64 + c * 16);
        uint32_t sw = SMEM_SWIZZLE_128B(off);
        size_t go = (size_t)n * 512 + (size_t)kt * 64 + c * 16;   // bytes
        CP_ASYNC16(wbuf + sw, (const char*)g_Wf + go);
    }
    CP_COMMIT();
}

__global__ void __launch_bounds__(256, 2)
gemm_ln_kernel(const float* __restrict__ A,
               const int* __restrict__ batch_ids, int N) {
    extern __shared__ char sm[];
    uint32_t smb = smem_to_u32(sm);
    float* s_sum = (float*)(sm + SM_ST);        // [64]
    float* s_sq  = (float*)(sm + SM_ST + 256);  // [64]

    int tid = threadIdx.x;
    int wid = tid >> 5, lane = tid & 31;
    int mw = wid >> 2;           // 0..1  m-warp
    int nw = wid & 3;            // 0..3  n-warp
    int m0 = blockIdx.x * 64;

    if (tid < 128) ((float*)(sm + SM_ST))[tid] = 0.0f;

    // ldmatrix per-lane addressing
    int g = lane >> 3;
    int lr = lane & 7;
    uint32_t axor = (uint32_t)(lr << 4);
    uint32_t a_row[2];
#pragma unroll
    for (int tm = 0; tm < 2; tm++)
        a_row[tm] = (uint32_t)((tm * 16 + (g & 1) * 8 + lr) * 128);
    uint32_t a_low_base = (uint32_t)(mw * 64 + (g >> 1) * 16);
    uint32_t b_row[4];
#pragma unroll
    for (int np = 0; np < 4; np++)
        b_row[np] = (uint32_t)((((nw & 1) * 64 + np * 16 + ((g >> 1) & 1) * 8 + lr)) * 128);
    uint32_t b_low_base = (uint32_t)((nw >> 1) * 64 + (g & 1) * 16);

    // A prefetch mapping
    int pm = tid >> 2;
    int prow = m0 + pm;
    const float* aptr = A + (size_t)prow * 256 + (tid & 3) * 8;
    bool pvalid = (prow < N);
    uint32_t a_st_off = SMEM_SWIZZLE_128B(
        (uint32_t)((pm & 31) * 128 + (pm >> 5) * 64 + (tid & 3) * 16));

    float c[2][8][4];
#pragma unroll
    for (int i = 0; i < 2; i++)
#pragma unroll
        for (int j = 0; j < 8; j++)
#pragma unroll
            for (int q = 0; q < 4; q++) c[i][j][q] = 0.0f;

    // ---- prologue
    issue_w_chunk(smb + SM_W0, 0, tid);
    issue_w_chunk(smb + SM_W1, 1, tid);
    float4 aP0 = make_float4(0.f, 0.f, 0.f, 0.f);
    float4 aP1 = make_float4(0.f, 0.f, 0.f, 0.f);
    if (pvalid) {
        aP0 = *(const float4*)(aptr);
        aP1 = *(const float4*)(aptr + 4);
    }

    for (int kt = 0; kt < 8; kt++) {
        if (kt > 0) __syncthreads();
        if (kt >= 1 && kt + 1 < 8)
            issue_w_chunk(smb + SM_W0 + ((kt + 1) & 1) * 16384, kt + 1, tid);

        // store converted A(kt) fp16
        {
            float f[8] = {aP0.x, aP0.y, aP0.z, aP0.w, aP1.x, aP1.y, aP1.z, aP1.w};
            uint32_t h[4];
#pragma unroll
            for (int q = 0; q < 4; q++) {
                __half h0 = __float2half_rn(f[2 * q]);
                __half h1 = __float2half_rn(f[2 * q + 1]);
                h[q] = ((uint32_t)__half_as_ushort(h1) << 16) | __half_as_ushort(h0);
            }
            *(uint4*)(sm + SM_AH + a_st_off) = make_uint4(h[0], h[1], h[2], h[3]);
        }

        if (kt == 7) { CP_WAIT0(); } else { CP_WAIT1(); }
        __syncthreads();

        if (kt + 1 < 8 && pvalid) {
            aP0 = *(const float4*)(aptr + (kt + 1) * 32);
            aP1 = *(const float4*)(aptr + (kt + 1) * 32 + 4);
        }

        uint32_t wb = smb + SM_W0 + (kt & 1) * 16384;
#pragma unroll
        for (int ks = 0; ks < 2; ks++) {
            uint32_t alow = (a_low_base + (uint32_t)(ks * 32)) ^ axor;
            uint32_t blow = (b_low_base + (uint32_t)(ks * 32)) ^ axor;
            uint32_t ah0[4], ah1[4];
            ldsm_x4(ah0, smb + SM_AH + a_row[0] + alow);
            ldsm_x4(ah1, smb + SM_AH + a_row[1] + alow);
            uint32_t bf[4][4];
#pragma unroll
            for (int np = 0; np < 4; np++)
                ldsm_x4(bf[np], wb + b_row[np] + blow);

            // 16 independent accumulators per warp
#pragma unroll
            for (int np = 0; np < 4; np++) {
                mma16816(c[0][2 * np],     ah0, bf[np]);
                mma16816(c[0][2 * np + 1], ah0, bf[np] + 2);
                mma16816(c[1][2 * np],     ah1, bf[np]);
                mma16816(c[1][2 * np + 1], ah1, bf[np] + 2);
            }
        }
    }

    // ---- LN stats: quad-shuffle partials, smem atomics across n-warps ----
#pragma unroll
    for (int tm = 0; tm < 2; tm++) {
#pragma unroll
        for (int h = 0; h < 2; h++) {
            int rl = mw * 32 + tm * 16 + h * 8 + (lane >> 2);
            float ps = 0.f, pq = 0.f;
#pragma unroll
            for (int nt = 0; nt < 8; nt++) {
                float v0 = c[tm][nt][2 * h], v1 = c[tm][nt][2 * h + 1];
                ps += v0 + v1;
                pq = fmaf(v0, v0, fmaf(v1, v1, pq));
            }
            ps += __shfl_xor_sync(0xffffffffu, ps, 1);
            pq += __shfl_xor_sync(0xffffffffu, pq, 1);
            ps += __shfl_xor_sync(0xffffffffu, ps, 2);
            pq += __shfl_xor_sync(0xffffffffu, pq, 2);
            if ((lane & 3) == 0) {
                atomicAdd(&s_sum[rl], ps);
                atomicAdd(&s_sq[rl], pq);
            }
        }
    }
    __syncthreads();

    // ---- normalize + FiLM + ReLU from fragments -> g_xh (fp16) ----
#pragma unroll
    for (int tm = 0; tm < 2; tm++) {
#pragma unroll
        for (int h = 0; h < 2; h++) {
            int rl = mw * 32 + tm * 16 + h * 8 + (lane >> 2);
            int row = m0 + rl;
            if (row >= N) continue;
            float mu = s_sum[rl] * (1.0f / 256.0f);
            float var = fmaxf(s_sq[rl] * (1.0f / 256.0f) - mu * mu, 0.0f);
            float rs = rsqrtf(var + 1e-5f);
            int b = batch_ids[row];
            const float* gg = g_gamma + b * 256;
            const float* bb = g_beta + b * 256;
            __half2* xo = (__half2*)(g_xh + (size_t)row * 256);
#pragma unroll
            for (int nt = 0; nt < 8; nt++) {
                int col = nw * 64 + nt * 8 + (lane & 3) * 2;
                float2 gv = *(const float2*)(gg + col);
                float2 ev = *(const float2*)(bb + col);
                float2 o;
                o.x = fmaxf(fmaf((c[tm][nt][2 * h] - mu) * rs, gv.x, ev.x), 0.f);
                o.y = fmaxf(fmaf((c[tm][nt][2 * h + 1] - mu) * rs, gv.y, ev.y), 0.f);
                xo[col >> 1] = __float22half2_rn(o);
            }
        }
    }
}

// ---------------------------------------------------------------------------
// 6. Pull aggregation: warp per node, coalesced edge fetch + shfl broadcast.
// ---------------------------------------------------------------------------
__global__ void agg_kernel(float* __restrict__ out, int N) {
    int gw = (blockIdx.x * blockDim.x + threadIdx.x) >> 5;
    int lane = threadIdx.x & 31;
    if (gw >= N) return;
    int s = g_off[gw];
    int e = g_off[gw + 1];
    float acc[8] = {0.f, 0.f, 0.f, 0.f, 0.f, 0.f, 0.f, 0.f};

    for (int base = s; base < e; base += 32) {
        int cnt = min(32, e - base);
        int2 my = (lane < cnt) ? g_edge[base + lane] : make_int2(0, 0);
        int j = 0;
        for (; j + 2 <= cnt; j += 2) {
            int s0 = __shfl_sync(0xffffffffu, my.x, j);
            int w0i = __shfl_sync(0xffffffffu, my.y, j);
            int s1 = __shfl_sync(0xffffffffu, my.x, j + 1);
            int w1i = __shfl_sync(0xffffffffu, my.y, j + 1);
            uint4 v0 = *(const uint4*)((const char*)g_xh + (size_t)s0 * 512 + lane * 16);
            uint4 v1 = *(const uint4*)((const char*)g_xh + (size_t)s1 * 512 + lane * 16);
            float w0 = __int_as_float(w0i);
            float w1 = __int_as_float(w1i);
            const __half2* h0 = (const __half2*)&v0;
            const __half2* h1 = (const __half2*)&v1;
#pragma unroll
            for (int q = 0; q < 4; q++) {
                float2 f0 = __half22float2(h0[q]);
                float2 f1 = __half22float2(h1[q]);
                acc[2 * q]     = fmaf(f0.x, w0, fmaf(f1.x, w1, acc[2 * q]));
                acc[2 * q + 1] = fmaf(f0.y, w0, fmaf(f1.y, w1, acc[2 * q + 1]));
            }
        }
        if (j < cnt) {
            int s0 = __shfl_sync(0xffffffffu, my.x, j);
            int w0i = __shfl_sync(0xffffffffu, my.y, j);
            uint4 v0 = *(const uint4*)((const char*)g_xh + (size_t)s0 * 512 + lane * 16);
            float w0 = __int_as_float(w0i);
            const __half2* h0 = (const __half2*)&v0;
#pragma unroll
            for (int q = 0; q < 4; q++) {
                float2 f0 = __half22float2(h0[q]);
                acc[2 * q]     = fmaf(f0.x, w0, acc[2 * q]);
                acc[2 * q + 1] = fmaf(f0.y, w0, acc[2 * q + 1]);
            }
        }
    }

    float4 o0, o1;
    o0.x = fmaxf(acc[0], 0.f); o0.y = fmaxf(acc[1], 0.f);
    o0.z = fmaxf(acc[2], 0.f); o0.w = fmaxf(acc[3], 0.f);
    o1.x = fmaxf(acc[4], 0.f); o1.y = fmaxf(acc[5], 0.f);
    o1.z = fmaxf(acc[6], 0.f); o1.w = fmaxf(acc[7], 0.f);
    float4* o4 = (float4*)(out + (size_t)gw * 256 + lane * 8);
    o4[0] = o0;
    o4[1] = o1;
}

// ---------------------------------------------------------------------------
extern "C" void kernel_launch(void* const* d_in, const int* in_sizes, int n_in,
                              void* d_out, int out_size) {
    const float* node_feats = (const float*)d_in[0];
    const float* cond_feats = (const float*)d_in[1];
    const int*   batch_ids  = (const int*)d_in[2];
    const int*   node_j     = (const int*)d_in[3];
    const int*   node_i     = (const int*)d_in[4];
    const float* edge_w     = (const float*)d_in[5];
    const float* edge_p     = (const float*)d_in[6];
    const float* Wc         = (const float*)d_in[7];
    const float* bc         = (const float*)d_in[8];
    const float* Wl         = (const float*)d_in[9];
    float* out = (float*)d_out;

    int N = in_sizes[0] / 256;
    int B = in_sizes[1] / 512;
    int E = in_sizes[3];
    int nblk = (N + 255) / 256;

    static cudaStream_t s2 = nullptr;
    static cudaEvent_t evF = nullptr, evJ = nullptr;
    if (!s2) {
        cudaStreamCreateWithFlags(&s2, cudaStreamNonBlocking);
        cudaEventCreateWithFlags(&evF, cudaEventDisableTiming);
        cudaEventCreateWithFlags(&evJ, cudaEventDisableTiming);
        cudaFuncSetAttribute(gemm_ln_kernel,
                             cudaFuncAttributeMaxDynamicSharedMemorySize, SM_TOTAL);
    }

    // main: prep(zero+W+film) -> gemm -> [join] -> agg
    // side (forked after prep): hist -> scan(lookback) -> fill
    prep_kernel<<<96, 256>>>(Wl, cond_feats, Wc, bc, B, N);
    cudaEventRecord(evF, 0);
    cudaStreamWaitEvent(s2, evF, 0);

    hist_kernel<<<(E + 255) / 256, 256, 0, s2>>>(node_i, E);
    scan_kernel<<<nblk, 256, 0, s2>>>(N, E);
    fill_kernel<<<(E + 255) / 256, 256, 0, s2>>>(node_i, node_j, edge_w, edge_p, E);
    cudaEventRecord(evJ, s2);

    gemm_ln_kernel<<<(N + 63) / 64, 256, SM_TOTAL>>>(node_feats, batch_ids, N);

    cudaStreamWaitEvent(0, evJ, 0);
    agg_kernel<<<(N * 32 + 255) / 256, 256>>>(out, N);
}